// round 1
// baseline (speedup 1.0000x reference)
#include <cuda_runtime.h>

// ---------------- problem constants ----------------
#define NB    2048          // batch
#define NEMB  256           // embedding dim
#define ND    64            // head dim
#define NH    16            // heads
#define NS    32            // pseudo-sequence / splits
#define HD    (NH * ND)     // 1024
#define SHD   (NS * HD)     // 32768

// ---------------- scratch (static device globals; no runtime alloc) ----------------
__device__ float g_q[NB * SHD];        // 256 MB  q[b][s][h][d]
__device__ float g_k[NB * SHD];        // 256 MB  k[b][t][h][d]
__device__ float g_v[NB * SHD];        // 256 MB  v[b][t][h][d]
__device__ float g_w[NB * HD];         // 8 MB    w[b][h*64+d]
__device__ float g_partial[NB * NH];   // per-(b,h) partial sums
__device__ float g_S[1];               // global scalar
__device__ int   g_idx[NB];            // normalized vocab indices

// ---------------- packed f32x2 helpers (Blackwell FFMA2) ----------------
__device__ __forceinline__ unsigned long long splat2(float x) {
    unsigned long long r;
    unsigned u = __float_as_uint(x);
    asm("mov.b64 %0, {%1, %1};" : "=l"(r) : "r"(u));
    return r;
}
__device__ __forceinline__ void fma2(unsigned long long& d,
                                     unsigned long long a,
                                     unsigned long long b) {
    asm("fma.rn.f32x2 %0, %1, %2, %0;" : "+l"(d) : "l"(a), "l"(b));
}
__device__ __forceinline__ float2 unpack2(unsigned long long v) {
    unsigned lo, hi;
    asm("mov.b64 {%0, %1}, %2;" : "=r"(lo), "=r"(hi) : "l"(v));
    float2 f;
    f.x = __uint_as_float(lo);
    f.y = __uint_as_float(hi);
    return f;
}

// ---------------- index normalization (handles int32 or int64 'd') ----------------
__global__ void prep_idx_kernel(const int* __restrict__ draw) {
    int i = blockIdx.x * blockDim.x + threadIdx.x;
    if (i >= NB) return;
    // If d is int64 (little-endian, values < 10000), every odd 32-bit word is 0.
    // Probability of false positive with random int32 values in [0,10000): ~1e-16.
    bool is64 = (draw[1] == 0) && (draw[3] == 0) && (draw[5] == 0) && (draw[7] == 0);
    g_idx[i] = is64 ? draw[2 * i] : draw[i];
}

// ---------------- tiled SGEMM: C[M,N] = A[M,K] @ B[K,N] + bias ----------------
// BM=BN=128, BK=8, 256 threads, 8x8 microtile packed as 8x4 f32x2 accumulators.
// GATHER: A row m is emb[g_idx[m]] (embedding lookup fused into the tile load).
// All dims are exact multiples of the tile sizes for this problem (no bounds checks).
template <bool GATHER>
__global__ __launch_bounds__(256)
void sgemm128_kernel(int M, int N, int K,
                     const float* __restrict__ A,
                     const float* __restrict__ B,
                     const float* __restrict__ bias,
                     float* __restrict__ C)
{
    __shared__ __align__(16) float As[8][128];   // [k][m] (transposed on store)
    __shared__ __align__(16) float Bs[8][128];   // [k][n]

    const int t  = threadIdx.x;
    const int tx = t & 15;        // 0..15 -> n microtile
    const int ty = t >> 4;        // 0..15 -> m microtile
    const int n0 = blockIdx.x * 128;
    const int m0 = blockIdx.y * 128;

    const int arow = t >> 1;          // 0..127
    const int aseg = (t & 1) * 4;     // 0 or 4
    const int brow = t >> 5;          // 0..7
    const int bcol = (t & 31) * 4;    // 0..124

    size_t arsrc = GATHER ? (size_t)g_idx[m0 + arow] : (size_t)(m0 + arow);
    const float* Ap = A + arsrc * (size_t)K + aseg;
    const float* Bp = B + (size_t)brow * N + n0 + bcol;

    unsigned long long acc[8][4];
#pragma unroll
    for (int i = 0; i < 8; i++)
#pragma unroll
        for (int j = 0; j < 4; j++) acc[i][j] = 0ull;

    for (int k0 = 0; k0 < K; k0 += 8) {
        float4 av = *(const float4*)(Ap + k0);
        float4 bv = *(const float4*)(Bp + (size_t)k0 * N);
        __syncthreads();
        As[aseg + 0][arow] = av.x;
        As[aseg + 1][arow] = av.y;
        As[aseg + 2][arow] = av.z;
        As[aseg + 3][arow] = av.w;
        *(float4*)&Bs[brow][bcol] = bv;
        __syncthreads();
#pragma unroll
        for (int kk = 0; kk < 8; kk++) {
            float4 a0 = *(const float4*)&As[kk][ty * 8];
            float4 a1 = *(const float4*)&As[kk][ty * 8 + 4];
            unsigned long long as2[8];
            as2[0] = splat2(a0.x); as2[1] = splat2(a0.y);
            as2[2] = splat2(a0.z); as2[3] = splat2(a0.w);
            as2[4] = splat2(a1.x); as2[5] = splat2(a1.y);
            as2[6] = splat2(a1.z); as2[7] = splat2(a1.w);
            ulonglong2 b0 = *(const ulonglong2*)&Bs[kk][tx * 8];
            ulonglong2 b1 = *(const ulonglong2*)&Bs[kk][tx * 8 + 4];
            unsigned long long bb2[4] = {b0.x, b0.y, b1.x, b1.y};
#pragma unroll
            for (int i = 0; i < 8; i++) {
#pragma unroll
                for (int j = 0; j < 4; j++) fma2(acc[i][j], as2[i], bb2[j]);
            }
        }
    }

    // epilogue: add bias, store
    const float* bp = bias + n0 + tx * 8;
    float bvv[8];
#pragma unroll
    for (int j = 0; j < 8; j++) bvv[j] = bp[j];
#pragma unroll
    for (int i = 0; i < 8; i++) {
        int m = m0 + ty * 8 + i;
        float out[8];
#pragma unroll
        for (int j = 0; j < 4; j++) {
            float2 f = unpack2(acc[i][j]);
            out[2 * j]     = f.x + bvv[2 * j];
            out[2 * j + 1] = f.y + bvv[2 * j + 1];
        }
        float* Cp = C + (size_t)m * N + n0 + tx * 8;
        *(float4*)Cp       = make_float4(out[0], out[1], out[2], out[3]);
        *(float4*)(Cp + 4) = make_float4(out[4], out[5], out[6], out[7]);
    }
}

// ---------------- fused attention + per-(b,h) reduce ----------------
// scores[s,t] = q[b,s,h,:] . k[b,t,h,:] / 8 ; probs = softmax_t ; c_t = sum_s probs
// out[d] = sum_t c_t * v[t,d] ; partial = sum_d leaky_relu(out[d]) * w[b,h*64+d]
__global__ __launch_bounds__(256)
void attention_kernel()
{
    const int b = blockIdx.x;
    const int h = blockIdx.y;
    __shared__ float qs[NS][ND + 1];
    __shared__ float ks[NS][ND + 1];
    __shared__ float vs[NS][ND + 1];
    __shared__ float ss[NS][NS + 1];
    __shared__ float cs[NS];
    __shared__ float red[ND];
    const int tid = threadIdx.x;

    const size_t base = (size_t)b * SHD + (size_t)h * ND;
    for (int i = tid; i < NS * (ND / 4); i += 256) {
        int s  = i >> 4;
        int c4 = (i & 15) * 4;
        size_t off = base + (size_t)s * HD + c4;
        float4 aq = *(const float4*)(g_q + off);
        float4 ak = *(const float4*)(g_k + off);
        float4 av = *(const float4*)(g_v + off);
        qs[s][c4 + 0] = aq.x; qs[s][c4 + 1] = aq.y; qs[s][c4 + 2] = aq.z; qs[s][c4 + 3] = aq.w;
        ks[s][c4 + 0] = ak.x; ks[s][c4 + 1] = ak.y; ks[s][c4 + 2] = ak.z; ks[s][c4 + 3] = ak.w;
        vs[s][c4 + 0] = av.x; vs[s][c4 + 1] = av.y; vs[s][c4 + 2] = av.z; vs[s][c4 + 3] = av.w;
    }
    __syncthreads();

    // scores: each thread computes 4 of the 32x32 scores
    {
        const int s  = tid >> 3;
        const int t0 = (tid & 7) * 4;
        float a0 = 0.f, a1 = 0.f, a2 = 0.f, a3 = 0.f;
#pragma unroll
        for (int dd = 0; dd < ND; dd++) {
            float qv = qs[s][dd];
            a0 = fmaf(qv, ks[t0 + 0][dd], a0);
            a1 = fmaf(qv, ks[t0 + 1][dd], a1);
            a2 = fmaf(qv, ks[t0 + 2][dd], a2);
            a3 = fmaf(qv, ks[t0 + 3][dd], a3);
        }
        const float sc = 0.125f;  // 1/sqrt(64)
        ss[s][t0 + 0] = a0 * sc;
        ss[s][t0 + 1] = a1 * sc;
        ss[s][t0 + 2] = a2 * sc;
        ss[s][t0 + 3] = a3 * sc;
    }
    __syncthreads();

    // softmax over t (one warp handles 4 rows)
    {
        const int w = tid >> 5, lane = tid & 31;
#pragma unroll
        for (int rr = 0; rr < 4; rr++) {
            int row = w * 4 + rr;
            float v = ss[row][lane];
            float m = v;
#pragma unroll
            for (int o = 16; o > 0; o >>= 1) m = fmaxf(m, __shfl_xor_sync(0xffffffffu, m, o));
            float e = __expf(v - m);
            float sum = e;
#pragma unroll
            for (int o = 16; o > 0; o >>= 1) sum += __shfl_xor_sync(0xffffffffu, sum, o);
            ss[row][lane] = e / sum;
        }
    }
    __syncthreads();

    // column sums c_t
    if (tid < NS) {
        float c = 0.f;
#pragma unroll
        for (int s = 0; s < NS; s++) c += ss[s][tid];
        cs[tid] = c;
    }
    __syncthreads();

    // out[d] = sum_t c_t v[t,d]; apply leaky_relu and w; stage per-d terms
    if (tid < ND) {
        float o = 0.f;
#pragma unroll
        for (int t2 = 0; t2 < NS; t2++) o = fmaf(cs[t2], vs[t2][tid], o);
        float wv = g_w[(size_t)b * HD + h * ND + tid];
        float lr = o > 0.0f ? o : 0.01f * o;
        red[tid] = lr * wv;
    }
    __syncthreads();

    if (tid == 0) {
        float sum = 0.f;
#pragma unroll
        for (int i = 0; i < ND; i++) sum += red[i];
        g_partial[b * NH + h] = sum;
    }
}

// ---------------- deterministic global reduce ----------------
__global__ void reduce_kernel()
{
    __shared__ float sm[1024];
    int tid = threadIdx.x;
    float s = 0.f;
    for (int i = tid; i < NB * NH; i += 1024) s += g_partial[i];
    sm[tid] = s;
    __syncthreads();
    for (int o = 512; o > 0; o >>= 1) {
        if (tid < o) sm[tid] += sm[tid + o];
        __syncthreads();
    }
    if (tid == 0) g_S[0] = sm[0];
}

// ---------------- final: out[i] = S + d2[i].Wb + bb ----------------
__global__ __launch_bounds__(256)
void final_kernel(const float* __restrict__ emb2,
                  const float* __restrict__ Wb,
                  const float* __restrict__ bb,
                  float* __restrict__ out)
{
    int gw   = (blockIdx.x * blockDim.x + threadIdx.x) >> 5;  // one warp per output
    int lane = threadIdx.x & 31;
    if (gw >= NB) return;
    const float* e2 = emb2 + (size_t)g_idx[gw] * NEMB;
    float s = 0.f;
    for (int k = lane; k < NEMB; k += 32) s = fmaf(e2[k], Wb[k], s);
#pragma unroll
    for (int o = 16; o > 0; o >>= 1) s += __shfl_xor_sync(0xffffffffu, s, o);
    if (lane == 0) out[gw] = g_S[0] + s + bb[0];
}

// ---------------- launch ----------------
extern "C" void kernel_launch(void* const* d_in, const int* in_sizes, int n_in,
                              void* d_out, int out_size)
{
    const float* r    = (const float*)d_in[0];
    const int*   draw = (const int*)  d_in[1];   // d (int32 or int64; normalized on device)
    const float* emb1 = (const float*)d_in[2];
    const float* emb2 = (const float*)d_in[3];
    const float* Wq   = (const float*)d_in[4];
    const float* bq   = (const float*)d_in[5];
    const float* Wk   = (const float*)d_in[6];
    const float* bk   = (const float*)d_in[7];
    const float* Wv   = (const float*)d_in[8];
    const float* bv   = (const float*)d_in[9];
    const float* Wb   = (const float*)d_in[10];
    const float* bb   = (const float*)d_in[11];
    const float* Ww   = (const float*)d_in[12];
    const float* bw   = (const float*)d_in[13];
    float* out = (float*)d_out;
    (void)in_sizes; (void)n_in; (void)out_size;

    float *pq, *pk, *pv, *pw;
    cudaGetSymbolAddress((void**)&pq, g_q);
    cudaGetSymbolAddress((void**)&pk, g_k);
    cudaGetSymbolAddress((void**)&pv, g_v);
    cudaGetSymbolAddress((void**)&pw, g_w);

    prep_idx_kernel<<<(NB + 255) / 256, 256>>>(draw);

    // q = emb1[d] @ Wq + bq   [2048 x 32768], K=256
    sgemm128_kernel<true ><<<dim3(SHD / 128, NB / 128), 256>>>(NB, SHD, NEMB, emb1, Wq, bq, pq);
    // k = r3 @ Wk + bk        [65536 x 1024], K=64
    sgemm128_kernel<false><<<dim3(HD / 128, (NB * NS) / 128), 256>>>(NB * NS, HD, ND, r, Wk, bk, pk);
    // v = r3 @ Wv + bv
    sgemm128_kernel<false><<<dim3(HD / 128, (NB * NS) / 128), 256>>>(NB * NS, HD, ND, r, Wv, bv, pv);
    // w = emb2[d] @ Ww + bw   [2048 x 1024], K=256
    sgemm128_kernel<true ><<<dim3(HD / 128, NB / 128), 256>>>(NB, HD, NEMB, emb2, Ww, bw, pw);

    attention_kernel<<<dim3(NB, NH), 256>>>();
    reduce_kernel<<<1, 1024>>>();
    final_kernel<<<(NB * 32) / 256, 256>>>(emb2, Wb, bb, out);
}

// round 3
// speedup vs baseline: 1.0785x; 1.0785x over previous
#include <cuda_runtime.h>
#include <cuda_bf16.h>
#include <cstdint>

// ---------------- problem constants ----------------
#define NB    2048
#define NEMB  256
#define ND    64
#define NH    16
#define NS    32
#define HD    (NH * ND)     // 1024
#define SHD   (NS * HD)     // 32768

// ---------------- scratch (static device globals) ----------------
__device__ float g_q[(size_t)NB * SHD];          // 256 MB
__device__ float g_k[(size_t)NB * NS * HD];      // 256 MB
__device__ float g_w[(size_t)NB * HD];           // 8 MB
__device__ float g_u[(size_t)NB * NH * ND];      // 8 MB
__device__ float g_partial[NB * NH];
__device__ float g_S[1];
__device__ int   g_idx[NB];

// bf16 split operands (16B aligned for cp.async / uint4)
__device__ __align__(16) __nv_bfloat16 gA1h[NB * NEMB], gA1l[NB * NEMB];
__device__ __align__(16) __nv_bfloat16 gA2h[NB * NEMB], gA2l[NB * NEMB];
__device__ __align__(16) __nv_bfloat16 gRh[(size_t)NB * NS * ND], gRl[(size_t)NB * NS * ND];
__device__ __align__(16) __nv_bfloat16 gBqh[(size_t)SHD * NEMB], gBql[(size_t)SHD * NEMB];
__device__ __align__(16) __nv_bfloat16 gBkh[HD * ND],   gBkl[HD * ND];
__device__ __align__(16) __nv_bfloat16 gBwh[HD * NEMB], gBwl[HD * NEMB];

// ---------------- helpers ----------------
__device__ __forceinline__ uint32_t smem_to_u32(const void* p) {
    uint32_t a;
    asm("{ .reg .u64 t; cvta.to.shared.u64 t, %1; cvt.u32.u64 %0, t; }" : "=r"(a) : "l"(p));
    return a;
}
__device__ __forceinline__ void cp_async16(uint32_t saddr, const void* gaddr) {
    asm volatile("cp.async.cg.shared.global [%0], [%1], 16;" :: "r"(saddr), "l"(gaddr));
}
__device__ __forceinline__ void cp_commit() {
    asm volatile("cp.async.commit_group;" ::: "memory");
}

// ---------------- prep kernels ----------------
__global__ void prep_idx_kernel(const int* __restrict__ draw) {
    int i = blockIdx.x * blockDim.x + threadIdx.x;
    if (i >= NB) return;
    bool is64 = (draw[1] == 0) && (draw[3] == 0) && (draw[5] == 0) && (draw[7] == 0);
    g_idx[i] = is64 ? draw[2 * i] : draw[i];
}

__device__ __forceinline__ void split_bf16(float x, __nv_bfloat16& h, __nv_bfloat16& l) {
    h = __float2bfloat16(x);
    l = __float2bfloat16(x - __bfloat162float(h));
}

__global__ __launch_bounds__(NEMB)
void gather_split_kernel(const float* __restrict__ emb1, const float* __restrict__ emb2) {
    int b = blockIdx.x, t = threadIdx.x;
    size_t src = (size_t)g_idx[b] * NEMB + t;
    size_t dst = (size_t)b * NEMB + t;
    split_bf16(emb1[src], gA1h[dst], gA1l[dst]);
    split_bf16(emb2[src], gA2h[dst], gA2l[dst]);
}

__global__ __launch_bounds__(256)
void split_r_kernel(const float* __restrict__ r) {
    size_t i = (size_t)blockIdx.x * 256 + threadIdx.x;      // float4 index
    float4 v = ((const float4*)r)[i];
    size_t o = i * 4;
    split_bf16(v.x, gRh[o + 0], gRl[o + 0]);
    split_bf16(v.y, gRh[o + 1], gRl[o + 1]);
    split_bf16(v.z, gRh[o + 2], gRl[o + 2]);
    split_bf16(v.w, gRh[o + 3], gRl[o + 3]);
}

// W [K][N] fp32 -> Th/Tl [N][K] bf16 (transpose + hi/lo split)
__global__ __launch_bounds__(256)
void transpose_split_kernel(const float* __restrict__ W, __nv_bfloat16* __restrict__ Th,
                            __nv_bfloat16* __restrict__ Tl, int K, int N) {
    __shared__ float tile[32][33];
    int n0 = blockIdx.x * 32, k0 = blockIdx.y * 32;
    int tx = threadIdx.x & 31, ty = threadIdx.x >> 5;  // 32x8
#pragma unroll
    for (int j = 0; j < 32; j += 8)
        tile[ty + j][tx] = W[(size_t)(k0 + ty + j) * N + n0 + tx];
    __syncthreads();
#pragma unroll
    for (int j = 0; j < 32; j += 8) {
        float v = tile[tx][ty + j];
        size_t o = (size_t)(n0 + ty + j) * K + (k0 + tx);
        split_bf16(v, Th[o], Tl[o]);
    }
}

// ---------------- HMMA GEMM: C[M,N] = (Ah+Al)[M,K] @ (Bh+Bl)^T + bias ----------------
// A [M][K], BT [N][K], both bf16 K-major. Tile 128x128, BK=64, cp.async double-buffer.
// 3-chunk hi/lo split: (Ah,Bh), (Al,Bh), (Ah,Bl). cp = K/64 segments per chunk.
__global__ __launch_bounds__(256, 2)
void hmma_gemm(const __nv_bfloat16* __restrict__ Ah, const __nv_bfloat16* __restrict__ Al,
               const __nv_bfloat16* __restrict__ Bh, const __nv_bfloat16* __restrict__ Bl,
               const float* __restrict__ bias, float* __restrict__ C,
               int N, int K, int cp)
{
    extern __shared__ __align__(128) char smem[];
    const int tid  = threadIdx.x;
    const int warp = tid >> 5, lane = tid & 31;
    const int wm = warp >> 2, wn = warp & 3;     // 2 x 4 warp grid, warp tile 64x32
    const int m0 = blockIdx.y * 128, n0 = blockIdx.x * 128;
    const int nc = 3 * cp;
    const uint32_t sbase = smem_to_u32(smem);

    float acc[4][4][4];
#pragma unroll
    for (int i = 0; i < 4; i++)
#pragma unroll
        for (int j = 0; j < 4; j++)
#pragma unroll
            for (int t = 0; t < 4; t++) acc[i][j][t] = 0.f;

    const int lrow = tid >> 3;   // 0..31 (row base, +32*i)
    const int lc8  = tid & 7;    // 16B chunk within 128B row

    auto issue_loads = [&](int c, int buf) {
        int part = c / cp;
        int k0 = (c - part * cp) * 64;
        const __nv_bfloat16* As = (part == 1) ? Al : Ah;
        const __nv_bfloat16* Bs = (part == 2) ? Bl : Bh;
        uint32_t sA = sbase + (uint32_t)buf * 32768u;
        uint32_t sB = sA + 16384u;
#pragma unroll
        for (int i = 0; i < 4; i++) {
            int row = lrow + i * 32;
            uint32_t soff = (uint32_t)row * 128u + (uint32_t)((lc8 ^ (row & 7)) << 4);
            cp_async16(sA + soff, As + (size_t)(m0 + row) * K + k0 + lc8 * 8);
            cp_async16(sB + soff, Bs + (size_t)(n0 + row) * K + k0 + lc8 * 8);
        }
        cp_commit();
    };

    auto compute = [&](int buf) {
        uint32_t sA = sbase + (uint32_t)buf * 32768u;
        uint32_t sB = sA + 16384u;
        const int lr8  = (lane & 7) + ((lane >> 3) & 1) * 8;  // row within 16-row tile
        const int lchi = lane >> 4;                            // k-half select
#pragma unroll
        for (int ks = 0; ks < 4; ks++) {
            uint32_t a[4][4], b[2][4];
            int chunk = ks * 2 + lchi;
#pragma unroll
            for (int mt = 0; mt < 4; mt++) {
                int row = wm * 64 + mt * 16 + lr8;
                uint32_t addr = sA + (uint32_t)row * 128u + (uint32_t)((chunk ^ (row & 7)) << 4);
                asm volatile("ldmatrix.sync.aligned.m8n8.x4.shared.b16 {%0,%1,%2,%3}, [%4];"
                             : "=r"(a[mt][0]), "=r"(a[mt][1]), "=r"(a[mt][2]), "=r"(a[mt][3])
                             : "r"(addr));
            }
#pragma unroll
            for (int ng = 0; ng < 2; ng++) {
                int row = wn * 32 + ng * 16 + lr8;
                uint32_t addr = sB + (uint32_t)row * 128u + (uint32_t)((chunk ^ (row & 7)) << 4);
                asm volatile("ldmatrix.sync.aligned.m8n8.x4.shared.b16 {%0,%1,%2,%3}, [%4];"
                             : "=r"(b[ng][0]), "=r"(b[ng][1]), "=r"(b[ng][2]), "=r"(b[ng][3])
                             : "r"(addr));
            }
#pragma unroll
            for (int mt = 0; mt < 4; mt++) {
#pragma unroll
                for (int nj = 0; nj < 4; nj++) {
                    int ng = nj >> 1, half = nj & 1;
                    asm volatile(
                        "mma.sync.aligned.m16n8k16.row.col.f32.bf16.bf16.f32 "
                        "{%0,%1,%2,%3},{%4,%5,%6,%7},{%8,%9},{%0,%1,%2,%3};"
                        : "+f"(acc[mt][nj][0]), "+f"(acc[mt][nj][1]),
                          "+f"(acc[mt][nj][2]), "+f"(acc[mt][nj][3])
                        : "r"(a[mt][0]), "r"(a[mt][1]), "r"(a[mt][2]), "r"(a[mt][3]),
                          "r"(b[ng][half]), "r"(b[ng][half + 2]));
                }
            }
        }
    };

    issue_loads(0, 0);
    for (int c = 0; c < nc; c++) {
        if (c + 1 < nc) {
            issue_loads(c + 1, (c + 1) & 1);
            asm volatile("cp.async.wait_group 1;" ::: "memory");
        } else {
            asm volatile("cp.async.wait_group 0;" ::: "memory");
        }
        __syncthreads();
        compute(c & 1);
        __syncthreads();
    }

    // epilogue: add bias, store fp32
    const int er = lane >> 2;
    const int ec = (lane & 3) * 2;
#pragma unroll
    for (int mt = 0; mt < 4; mt++) {
        int row = m0 + wm * 64 + mt * 16 + er;
#pragma unroll
        for (int nj = 0; nj < 4; nj++) {
            int col = n0 + wn * 32 + nj * 8 + ec;
            float2 bv = *(const float2*)(bias + col);
            float2 o0, o1;
            o0.x = acc[mt][nj][0] + bv.x; o0.y = acc[mt][nj][1] + bv.y;
            o1.x = acc[mt][nj][2] + bv.x; o1.y = acc[mt][nj][3] + bv.y;
            *(float2*)(C + (size_t)row * N + col)       = o0;
            *(float2*)(C + (size_t)(row + 8) * N + col) = o1;
        }
    }
}

// ---------------- attention phase 1: scores/softmax/colsum -> u ----------------
__global__ __launch_bounds__(256)
void attention1_kernel(const float* __restrict__ r)
{
    const int b = blockIdx.x;
    __shared__ float r3s[NS][ND];
    __shared__ float qs[NS][ND + 4];
    __shared__ float ks[NS][ND + 4];
    __shared__ float ss[NS][NS + 1];
    __shared__ float cs[NS];
    const int tid = threadIdx.x;

    for (int i = tid; i < NS * ND / 4; i += 256) {
        int s = i >> 4, c4 = (i & 15) * 4;
        *(float4*)&r3s[s][c4] = *(const float4*)(r + (size_t)b * (NS * ND) + s * ND + c4);
    }

    for (int h = 0; h < NH; h++) {
        for (int i = tid; i < 512; i += 256) {
            int s = i >> 4, c4 = (i & 15) * 4;
            *(float4*)&qs[s][c4] = *(const float4*)(g_q + (size_t)b * SHD + (size_t)s * HD + h * ND + c4);
            *(float4*)&ks[s][c4] = *(const float4*)(g_k + ((size_t)b * NS + s) * HD + h * ND + c4);
        }
        __syncthreads();

        {
            const int s = tid >> 3, t0 = (tid & 7) * 4;
            float a0 = 0.f, a1 = 0.f, a2 = 0.f, a3 = 0.f;
#pragma unroll
            for (int dd = 0; dd < ND; dd++) {
                float qv = qs[s][dd];
                a0 = fmaf(qv, ks[t0 + 0][dd], a0);
                a1 = fmaf(qv, ks[t0 + 1][dd], a1);
                a2 = fmaf(qv, ks[t0 + 2][dd], a2);
                a3 = fmaf(qv, ks[t0 + 3][dd], a3);
            }
            ss[s][t0 + 0] = a0 * 0.125f;
            ss[s][t0 + 1] = a1 * 0.125f;
            ss[s][t0 + 2] = a2 * 0.125f;
            ss[s][t0 + 3] = a3 * 0.125f;
        }
        __syncthreads();

        {
            const int w = tid >> 5, lane = tid & 31;
#pragma unroll
            for (int rr = 0; rr < 4; rr++) {
                int row = w * 4 + rr;
                float v = ss[row][lane];
                float m = v;
#pragma unroll
                for (int o = 16; o > 0; o >>= 1) m = fmaxf(m, __shfl_xor_sync(0xffffffffu, m, o));
                float e = __expf(v - m);
                float sum = e;
#pragma unroll
                for (int o = 16; o > 0; o >>= 1) sum += __shfl_xor_sync(0xffffffffu, sum, o);
                ss[row][lane] = e / sum;
            }
        }
        __syncthreads();

        if (tid < NS) {
            float c = 0.f;
#pragma unroll
            for (int s = 0; s < NS; s++) c += ss[s][tid];
            cs[tid] = c;
        }
        __syncthreads();

        if (tid < ND) {
            float u = 0.f;
#pragma unroll
            for (int t2 = 0; t2 < NS; t2++) u = fmaf(cs[t2], r3s[t2][tid], u);
            g_u[((size_t)b * NH + h) * ND + tid] = u;
        }
        __syncthreads();
    }
}

// ---------------- attention phase 2: out = u @ Wv_h + 32*bv; leaky*w; per-(b,h) sum ----------------
__global__ __launch_bounds__(256)
void attention2_kernel(const float* __restrict__ Wv, const float* __restrict__ bv)
{
    __shared__ float wv[ND][ND + 1];
    __shared__ float bvs[ND];
    __shared__ float us[4][ND];
    __shared__ float wsum[8];
    const int h = blockIdx.x;
    const int bbase = blockIdx.y * 64;
    const int tid = threadIdx.x;

    for (int i = tid; i < ND * ND; i += 256) {
        int e = i >> 6, d2 = i & 63;
        wv[e][d2] = Wv[(size_t)e * HD + h * ND + d2];
    }
    if (tid < ND) bvs[tid] = 32.0f * bv[h * ND + tid];
    __syncthreads();

    const int sub = tid >> 6, d = tid & 63;
    for (int bi = 0; bi < 16; bi++) {
        int b = bbase + bi * 4 + sub;
        us[sub][d] = g_u[((size_t)b * NH + h) * ND + d];
        __syncthreads();
        float o = bvs[d];
#pragma unroll
        for (int e = 0; e < ND; e++) o = fmaf(us[sub][e], wv[e][d], o);
        float lr = o > 0.f ? o : 0.01f * o;
        float term = lr * g_w[(size_t)b * HD + h * ND + d];
#pragma unroll
        for (int off = 16; off > 0; off >>= 1) term += __shfl_xor_sync(0xffffffffu, term, off);
        if ((tid & 31) == 0) wsum[tid >> 5] = term;
        __syncthreads();
        if (d == 0) g_partial[(size_t)b * NH + h] = wsum[sub * 2] + wsum[sub * 2 + 1];
        __syncthreads();
    }
}

// ---------------- deterministic global reduce ----------------
__global__ void reduce_kernel()
{
    __shared__ float smr[1024];
    int tid = threadIdx.x;
    float s = 0.f;
    for (int i = tid; i < NB * NH; i += 1024) s += g_partial[i];
    smr[tid] = s;
    __syncthreads();
    for (int o = 512; o > 0; o >>= 1) {
        if (tid < o) smr[tid] += smr[tid + o];
        __syncthreads();
    }
    if (tid == 0) g_S[0] = smr[0];
}

// ---------------- final: out[i] = S + d2[i].Wb + bb ----------------
__global__ __launch_bounds__(256)
void final_kernel(const float* __restrict__ emb2, const float* __restrict__ Wb,
                  const float* __restrict__ bb, float* __restrict__ out)
{
    int gw   = (blockIdx.x * blockDim.x + threadIdx.x) >> 5;
    int lane = threadIdx.x & 31;
    if (gw >= NB) return;
    const float* e2 = emb2 + (size_t)g_idx[gw] * NEMB;
    float s = 0.f;
    for (int k = lane; k < NEMB; k += 32) s = fmaf(e2[k], Wb[k], s);
#pragma unroll
    for (int o = 16; o > 0; o >>= 1) s += __shfl_xor_sync(0xffffffffu, s, o);
    if (lane == 0) out[gw] = g_S[0] + s + bb[0];
}

// ---------------- launch ----------------
extern "C" void kernel_launch(void* const* d_in, const int* in_sizes, int n_in,
                              void* d_out, int out_size)
{
    const float* r    = (const float*)d_in[0];
    const int*   draw = (const int*)  d_in[1];
    const float* emb1 = (const float*)d_in[2];
    const float* emb2 = (const float*)d_in[3];
    const float* Wq   = (const float*)d_in[4];
    const float* bq   = (const float*)d_in[5];
    const float* Wk   = (const float*)d_in[6];
    const float* bk   = (const float*)d_in[7];
    const float* Wv   = (const float*)d_in[8];
    const float* bv   = (const float*)d_in[9];
    const float* Wb   = (const float*)d_in[10];
    const float* bb   = (const float*)d_in[11];
    const float* Ww   = (const float*)d_in[12];
    const float* bw   = (const float*)d_in[13];
    float* out = (float*)d_out;
    (void)in_sizes; (void)n_in; (void)out_size;

    float *pq, *pk, *pw;
    cudaGetSymbolAddress((void**)&pq, g_q);
    cudaGetSymbolAddress((void**)&pk, g_k);
    cudaGetSymbolAddress((void**)&pw, g_w);
    __nv_bfloat16 *a1h, *a1l, *a2h, *a2l, *rh, *rl, *bqh, *bql, *bkh, *bkl, *bwh, *bwl;
    cudaGetSymbolAddress((void**)&a1h, gA1h); cudaGetSymbolAddress((void**)&a1l, gA1l);
    cudaGetSymbolAddress((void**)&a2h, gA2h); cudaGetSymbolAddress((void**)&a2l, gA2l);
    cudaGetSymbolAddress((void**)&rh,  gRh);  cudaGetSymbolAddress((void**)&rl,  gRl);
    cudaGetSymbolAddress((void**)&bqh, gBqh); cudaGetSymbolAddress((void**)&bql, gBql);
    cudaGetSymbolAddress((void**)&bkh, gBkh); cudaGetSymbolAddress((void**)&bkl, gBkl);
    cudaGetSymbolAddress((void**)&bwh, gBwh); cudaGetSymbolAddress((void**)&bwl, gBwl);

    const int GEMM_SMEM = 65536;  // 2 stages x (16KB A + 16KB B)
    cudaFuncSetAttribute(hmma_gemm, cudaFuncAttributeMaxDynamicSharedMemorySize, GEMM_SMEM);

    prep_idx_kernel<<<(NB + 255) / 256, 256>>>(draw);
    gather_split_kernel<<<NB, NEMB>>>(emb1, emb2);
    split_r_kernel<<<(NB * NS * ND) / (256 * 4), 256>>>(r);
    transpose_split_kernel<<<dim3(SHD / 32, NEMB / 32), 256>>>(Wq, bqh, bql, NEMB, SHD);
    transpose_split_kernel<<<dim3(HD / 32, ND / 32),   256>>>(Wk, bkh, bkl, ND,   HD);
    transpose_split_kernel<<<dim3(HD / 32, NEMB / 32), 256>>>(Ww, bwh, bwl, NEMB, HD);

    // q = emb1[d] @ Wq + bq : M=2048, N=32768, K=256
    hmma_gemm<<<dim3(SHD / 128, NB / 128), 256, GEMM_SMEM>>>(a1h, a1l, bqh, bql, bq, pq, SHD, NEMB, NEMB / 64);
    // k = r3 @ Wk + bk : M=65536, N=1024, K=64
    hmma_gemm<<<dim3(HD / 128, (NB * NS) / 128), 256, GEMM_SMEM>>>(rh, rl, bkh, bkl, bk, pk, HD, ND, 1);
    // w = emb2[d] @ Ww + bw : M=2048, N=1024, K=256
    hmma_gemm<<<dim3(HD / 128, NB / 128), 256, GEMM_SMEM>>>(a2h, a2l, bwh, bwl, bw, pw, HD, NEMB, NEMB / 64);

    attention1_kernel<<<NB, 256>>>(r);
    attention2_kernel<<<dim3(NH, NB / 64), 256>>>(Wv, bv);
    reduce_kernel<<<1, 1024>>>();
    final_kernel<<<(NB * 32) / 256, 256>>>(emb2, Wb, bb, out);
}

// round 5
// speedup vs baseline: 1.8857x; 1.7485x over previous
#include <cuda_runtime.h>
#include <cuda_bf16.h>
#include <cstdint>

// ---------------- problem constants ----------------
#define NB    2048
#define NEMB  256
#define ND    64
#define NH    16
#define NS    32
#define HD    (NH * ND)     // 1024
#define SHD   (NS * HD)     // 32768

// ---------------- scratch (static device globals) ----------------
__device__ __align__(16) __nv_bfloat16 g_q[(size_t)NB * SHD];      // 134 MB
__device__ __align__(16) __nv_bfloat16 g_k[(size_t)NB * NS * HD];  // 134 MB
__device__ float g_w[(size_t)NB * HD];           // 8 MB (fp32: multiplies output directly)
__device__ float g_u[(size_t)NB * NH * ND];      // 8 MB
__device__ float g_partial[NB * NH];
__device__ float g_S[1];
__device__ int   g_idx[NB];

// bf16 operands
__device__ __align__(16) __nv_bfloat16 gA1[NB * NEMB];                    // emb1[d] single
__device__ __align__(16) __nv_bfloat16 gA2h[NB * NEMB], gA2l[NB * NEMB];  // emb2[d] split
__device__ __align__(16) __nv_bfloat16 gR[(size_t)NB * NS * ND];          // r single
__device__ __align__(16) __nv_bfloat16 gBq[(size_t)SHD * NEMB];           // Wq^T single
__device__ __align__(16) __nv_bfloat16 gBk[HD * ND];                      // Wk^T single
__device__ __align__(16) __nv_bfloat16 gBwh[HD * NEMB], gBwl[HD * NEMB];  // Ww^T split

// ---------------- helpers ----------------
__device__ __forceinline__ uint32_t smem_to_u32(const void* p) {
    uint32_t a;
    asm("{ .reg .u64 t; cvta.to.shared.u64 t, %1; cvt.u32.u64 %0, t; }" : "=r"(a) : "l"(p));
    return a;
}
__device__ __forceinline__ void cp_async16(uint32_t saddr, const void* gaddr) {
    asm volatile("cp.async.cg.shared.global [%0], [%1], 16;" :: "r"(saddr), "l"(gaddr));
}
__device__ __forceinline__ void cp_commit() {
    asm volatile("cp.async.commit_group;" ::: "memory");
}

// ---------------- prep kernels ----------------
__global__ void prep_idx_kernel(const int* __restrict__ draw) {
    int i = blockIdx.x * blockDim.x + threadIdx.x;
    if (i >= NB) return;
    bool is64 = (draw[1] == 0) && (draw[3] == 0) && (draw[5] == 0) && (draw[7] == 0);
    g_idx[i] = is64 ? draw[2 * i] : draw[i];
}

__device__ __forceinline__ void split_bf16(float x, __nv_bfloat16& h, __nv_bfloat16& l) {
    h = __float2bfloat16(x);
    l = __float2bfloat16(x - __bfloat162float(h));
}

__global__ __launch_bounds__(NEMB)
void gather_kernel(const float* __restrict__ emb1, const float* __restrict__ emb2) {
    int b = blockIdx.x, t = threadIdx.x;
    size_t src = (size_t)g_idx[b] * NEMB + t;
    size_t dst = (size_t)b * NEMB + t;
    gA1[dst] = __float2bfloat16(emb1[src]);
    split_bf16(emb2[src], gA2h[dst], gA2l[dst]);
}

__global__ __launch_bounds__(256)
void conv_r_kernel(const float* __restrict__ r) {
    size_t i = (size_t)blockIdx.x * 256 + threadIdx.x;      // float4 index
    float4 v = ((const float4*)r)[i];
    __nv_bfloat162 lo = __float22bfloat162_rn(make_float2(v.x, v.y));
    __nv_bfloat162 hi = __float22bfloat162_rn(make_float2(v.z, v.w));
    *(__nv_bfloat162*)(gR + i * 4)     = lo;
    *(__nv_bfloat162*)(gR + i * 4 + 2) = hi;
}

// W [K][N] fp32 -> Th(,Tl) [N][K] bf16 transpose
template <bool SPLIT>
__global__ __launch_bounds__(256)
void transpose_kernel(const float* __restrict__ W, __nv_bfloat16* __restrict__ Th,
                      __nv_bfloat16* __restrict__ Tl, int K, int N) {
    __shared__ float tile[32][33];
    int n0 = blockIdx.x * 32, k0 = blockIdx.y * 32;
    int tx = threadIdx.x & 31, ty = threadIdx.x >> 5;  // 32x8
#pragma unroll
    for (int j = 0; j < 32; j += 8)
        tile[ty + j][tx] = W[(size_t)(k0 + ty + j) * N + n0 + tx];
    __syncthreads();
#pragma unroll
    for (int j = 0; j < 32; j += 8) {
        float v = tile[tx][ty + j];
        size_t o = (size_t)(n0 + ty + j) * K + (k0 + tx);
        if (SPLIT) split_bf16(v, Th[o], Tl[o]);
        else       Th[o] = __float2bfloat16(v);
    }
}

// ---------------- HMMA GEMM ----------------
// C[M,N] = A[M,K] @ BT[N,K]^T + bias.  Tile 128x128, BK=64, cp.async double-buffer.
// SPLIT: 3-chunk hi/lo (AhBh, AlBh, AhBl). OT: float or __nv_bfloat16 output.
template <bool SPLIT, typename OT>
__global__ __launch_bounds__(256, 2)
void hmma_gemm(const __nv_bfloat16* __restrict__ Ah, const __nv_bfloat16* __restrict__ Al,
               const __nv_bfloat16* __restrict__ Bh, const __nv_bfloat16* __restrict__ Bl,
               const float* __restrict__ bias, OT* __restrict__ C,
               int N, int K, int cp)
{
    extern __shared__ __align__(128) char smem[];
    const int tid  = threadIdx.x;
    const int warp = tid >> 5, lane = tid & 31;
    const int wm = warp >> 2, wn = warp & 3;     // 2 x 4 warp grid, warp tile 64x32
    const int m0 = blockIdx.y * 128, n0 = blockIdx.x * 128;
    const int nc = SPLIT ? 3 * cp : cp;
    const uint32_t sbase = smem_to_u32(smem);

    float acc[4][4][4];
#pragma unroll
    for (int i = 0; i < 4; i++)
#pragma unroll
        for (int j = 0; j < 4; j++)
#pragma unroll
            for (int t = 0; t < 4; t++) acc[i][j][t] = 0.f;

    const int lrow = tid >> 3;   // 0..31 (row base, +32*i)
    const int lc8  = tid & 7;    // 16B chunk within 128B row

    auto issue_loads = [&](int c, int buf) {
        int part = SPLIT ? c / cp : 0;
        int k0 = (c - part * cp) * 64;
        const __nv_bfloat16* As = (part == 1) ? Al : Ah;
        const __nv_bfloat16* Bs = (part == 2) ? Bl : Bh;
        uint32_t sA = sbase + (uint32_t)buf * 32768u;
        uint32_t sB = sA + 16384u;
#pragma unroll
        for (int i = 0; i < 4; i++) {
            int row = lrow + i * 32;
            uint32_t soff = (uint32_t)row * 128u + (uint32_t)((lc8 ^ (row & 7)) << 4);
            cp_async16(sA + soff, As + (size_t)(m0 + row) * K + k0 + lc8 * 8);
            cp_async16(sB + soff, Bs + (size_t)(n0 + row) * K + k0 + lc8 * 8);
        }
        cp_commit();
    };

    auto compute = [&](int buf) {
        uint32_t sA = sbase + (uint32_t)buf * 32768u;
        uint32_t sB = sA + 16384u;
        const int lr8  = (lane & 7) + ((lane >> 3) & 1) * 8;
        const int lchi = lane >> 4;
#pragma unroll
        for (int ks = 0; ks < 4; ks++) {
            uint32_t a[4][4], b[2][4];
            int chunk = ks * 2 + lchi;
#pragma unroll
            for (int mt = 0; mt < 4; mt++) {
                int row = wm * 64 + mt * 16 + lr8;
                uint32_t addr = sA + (uint32_t)row * 128u + (uint32_t)((chunk ^ (row & 7)) << 4);
                asm volatile("ldmatrix.sync.aligned.m8n8.x4.shared.b16 {%0,%1,%2,%3}, [%4];"
                             : "=r"(a[mt][0]), "=r"(a[mt][1]), "=r"(a[mt][2]), "=r"(a[mt][3])
                             : "r"(addr));
            }
#pragma unroll
            for (int ng = 0; ng < 2; ng++) {
                int row = wn * 32 + ng * 16 + lr8;
                uint32_t addr = sB + (uint32_t)row * 128u + (uint32_t)((chunk ^ (row & 7)) << 4);
                asm volatile("ldmatrix.sync.aligned.m8n8.x4.shared.b16 {%0,%1,%2,%3}, [%4];"
                             : "=r"(b[ng][0]), "=r"(b[ng][1]), "=r"(b[ng][2]), "=r"(b[ng][3])
                             : "r"(addr));
            }
#pragma unroll
            for (int mt = 0; mt < 4; mt++) {
#pragma unroll
                for (int nj = 0; nj < 4; nj++) {
                    int ng = nj >> 1, half = nj & 1;
                    asm volatile(
                        "mma.sync.aligned.m16n8k16.row.col.f32.bf16.bf16.f32 "
                        "{%0,%1,%2,%3},{%4,%5,%6,%7},{%8,%9},{%0,%1,%2,%3};"
                        : "+f"(acc[mt][nj][0]), "+f"(acc[mt][nj][1]),
                          "+f"(acc[mt][nj][2]), "+f"(acc[mt][nj][3])
                        : "r"(a[mt][0]), "r"(a[mt][1]), "r"(a[mt][2]), "r"(a[mt][3]),
                          "r"(b[ng][half]), "r"(b[ng][half + 2]));
                }
            }
        }
    };

    issue_loads(0, 0);
    for (int c = 0; c < nc; c++) {
        if (c + 1 < nc) {
            issue_loads(c + 1, (c + 1) & 1);
            asm volatile("cp.async.wait_group 1;" ::: "memory");
        } else {
            asm volatile("cp.async.wait_group 0;" ::: "memory");
        }
        __syncthreads();
        compute(c & 1);
        __syncthreads();
    }

    // epilogue: add bias, store
    const int er = lane >> 2;
    const int ec = (lane & 3) * 2;
#pragma unroll
    for (int mt = 0; mt < 4; mt++) {
        int row = m0 + wm * 64 + mt * 16 + er;
#pragma unroll
        for (int nj = 0; nj < 4; nj++) {
            int col = n0 + wn * 32 + nj * 8 + ec;
            float2 bv = *(const float2*)(bias + col);
            float2 o0, o1;
            o0.x = acc[mt][nj][0] + bv.x; o0.y = acc[mt][nj][1] + bv.y;
            o1.x = acc[mt][nj][2] + bv.x; o1.y = acc[mt][nj][3] + bv.y;
            if (sizeof(OT) == 2) {
                *(__nv_bfloat162*)((__nv_bfloat16*)C + (size_t)row * N + col)       = __float22bfloat162_rn(o0);
                *(__nv_bfloat162*)((__nv_bfloat16*)C + (size_t)(row + 8) * N + col) = __float22bfloat162_rn(o1);
            } else {
                *(float2*)((float*)C + (size_t)row * N + col)       = o0;
                *(float2*)((float*)C + (size_t)(row + 8) * N + col) = o1;
            }
        }
    }
}

// ---------------- attention: one block per (b,h) ----------------
// scores -> softmax -> colsums c_t -> u[d] = sum_t c_t * r3[b,t,d] (fp32 r!)
__global__ __launch_bounds__(128)
void attention1_kernel(const float* __restrict__ r)
{
    const int b = blockIdx.x, h = blockIdx.y;
    __shared__ float qf[NS][ND + 2];
    __shared__ float kf[NS][ND + 2];
    __shared__ float r3s[NS][ND + 4];   // row stride 68 floats = 272B (16B-aligned) for float4 stores
    __shared__ float ss[NS][NS + 1];
    __shared__ float cs[NS];
    const int tid = threadIdx.x;
    const int s  = tid >> 2;
    const int d0 = (tid & 3) * 16;

    // load q,k (bf16, 16 elems/thread) and r3 (fp32)
    {
        const __nv_bfloat16* qp = g_q + (size_t)b * SHD + (size_t)s * HD + h * ND + d0;
        const __nv_bfloat16* kp = g_k + ((size_t)b * NS + s) * HD + h * ND + d0;
        uint4 qv[2], kv[2];
        qv[0] = *(const uint4*)qp;      qv[1] = *(const uint4*)(qp + 8);
        kv[0] = *(const uint4*)kp;      kv[1] = *(const uint4*)(kp + 8);
        const __nv_bfloat162* q2 = (const __nv_bfloat162*)qv;
        const __nv_bfloat162* k2 = (const __nv_bfloat162*)kv;
#pragma unroll
        for (int j = 0; j < 8; j++) {
            float2 f = __bfloat1622float2(q2[j]);
            qf[s][d0 + 2 * j] = f.x; qf[s][d0 + 2 * j + 1] = f.y;
            f = __bfloat1622float2(k2[j]);
            kf[s][d0 + 2 * j] = f.x; kf[s][d0 + 2 * j + 1] = f.y;
        }
        const float* rp = r + ((size_t)b * NS + s) * ND + d0;
#pragma unroll
        for (int j = 0; j < 4; j++)
            *(float4*)&r3s[s][d0 + 4 * j] = *(const float4*)(rp + 4 * j);
    }
    __syncthreads();

    // scores: each thread 8 of 32x32
    {
        const int t0 = (tid & 3) * 8;
        float a[8];
#pragma unroll
        for (int j = 0; j < 8; j++) a[j] = 0.f;
#pragma unroll
        for (int dd = 0; dd < ND; dd++) {
            float qv = qf[s][dd];
#pragma unroll
            for (int j = 0; j < 8; j++) a[j] = fmaf(qv, kf[t0 + j][dd], a[j]);
        }
#pragma unroll
        for (int j = 0; j < 8; j++) ss[s][t0 + j] = a[j] * 0.125f;
    }
    __syncthreads();

    // softmax per row: warp w handles rows w*8..w*8+7
    {
        const int w = tid >> 5, lane = tid & 31;
#pragma unroll
        for (int rr = 0; rr < 8; rr++) {
            int row = w * 8 + rr;
            float v = ss[row][lane];
            float m = v;
#pragma unroll
            for (int o = 16; o > 0; o >>= 1) m = fmaxf(m, __shfl_xor_sync(0xffffffffu, m, o));
            float e = __expf(v - m);
            float sum = e;
#pragma unroll
            for (int o = 16; o > 0; o >>= 1) sum += __shfl_xor_sync(0xffffffffu, sum, o);
            ss[row][lane] = e / sum;
        }
    }
    __syncthreads();

    if (tid < NS) {
        float c = 0.f;
#pragma unroll
        for (int s2 = 0; s2 < NS; s2++) c += ss[s2][tid];
        cs[tid] = c;
    }
    __syncthreads();

    if (tid < ND) {
        float u = 0.f;
#pragma unroll
        for (int t2 = 0; t2 < NS; t2++) u = fmaf(cs[t2], r3s[t2][tid], u);
        g_u[((size_t)b * NH + h) * ND + tid] = u;
    }
}

// ---------------- attention2: out = u @ Wv_h + 32*bv; leaky*w; per-(b,h) sum ----------------
__global__ __launch_bounds__(256)
void attention2_kernel(const float* __restrict__ Wv, const float* __restrict__ bv)
{
    __shared__ float wv[ND][ND + 1];
    __shared__ float bvs[ND];
    __shared__ float us[4][ND];
    __shared__ float wsum[8];
    const int h = blockIdx.x;
    const int bbase = blockIdx.y * 64;
    const int tid = threadIdx.x;

    for (int i = tid; i < ND * ND; i += 256) {
        int e = i >> 6, d2 = i & 63;
        wv[e][d2] = Wv[(size_t)e * HD + h * ND + d2];
    }
    if (tid < ND) bvs[tid] = 32.0f * bv[h * ND + tid];
    __syncthreads();

    const int sub = tid >> 6, d = tid & 63;
    for (int bi = 0; bi < 16; bi++) {
        int b = bbase + bi * 4 + sub;
        us[sub][d] = g_u[((size_t)b * NH + h) * ND + d];
        __syncthreads();
        float o = bvs[d];
#pragma unroll
        for (int e = 0; e < ND; e++) o = fmaf(us[sub][e], wv[e][d], o);
        float lr = o > 0.f ? o : 0.01f * o;
        float term = lr * g_w[(size_t)b * HD + h * ND + d];
#pragma unroll
        for (int off = 16; off > 0; off >>= 1) term += __shfl_xor_sync(0xffffffffu, term, off);
        if ((tid & 31) == 0) wsum[tid >> 5] = term;
        __syncthreads();
        if (d == 0) g_partial[(size_t)b * NH + h] = wsum[sub * 2] + wsum[sub * 2 + 1];
        __syncthreads();
    }
}

// ---------------- deterministic global reduce ----------------
__global__ void reduce_kernel()
{
    __shared__ float smr[1024];
    int tid = threadIdx.x;
    float s = 0.f;
    for (int i = tid; i < NB * NH; i += 1024) s += g_partial[i];
    smr[tid] = s;
    __syncthreads();
    for (int o = 512; o > 0; o >>= 1) {
        if (tid < o) smr[tid] += smr[tid + o];
        __syncthreads();
    }
    if (tid == 0) g_S[0] = smr[0];
}

// ---------------- final: out[i] = S + d2[i].Wb + bb ----------------
__global__ __launch_bounds__(256)
void final_kernel(const float* __restrict__ emb2, const float* __restrict__ Wb,
                  const float* __restrict__ bb, float* __restrict__ out)
{
    int gw   = (blockIdx.x * blockDim.x + threadIdx.x) >> 5;
    int lane = threadIdx.x & 31;
    if (gw >= NB) return;
    const float* e2 = emb2 + (size_t)g_idx[gw] * NEMB;
    float s = 0.f;
    for (int k = lane; k < NEMB; k += 32) s = fmaf(e2[k], Wb[k], s);
#pragma unroll
    for (int o = 16; o > 0; o >>= 1) s += __shfl_xor_sync(0xffffffffu, s, o);
    if (lane == 0) out[gw] = g_S[0] + s + bb[0];
}

// ---------------- launch ----------------
extern "C" void kernel_launch(void* const* d_in, const int* in_sizes, int n_in,
                              void* d_out, int out_size)
{
    const float* r    = (const float*)d_in[0];
    const int*   draw = (const int*)  d_in[1];
    const float* emb1 = (const float*)d_in[2];
    const float* emb2 = (const float*)d_in[3];
    const float* Wq   = (const float*)d_in[4];
    const float* bq   = (const float*)d_in[5];
    const float* Wk   = (const float*)d_in[6];
    const float* bk   = (const float*)d_in[7];
    const float* Wv   = (const float*)d_in[8];
    const float* bv   = (const float*)d_in[9];
    const float* Wb   = (const float*)d_in[10];
    const float* bb   = (const float*)d_in[11];
    const float* Ww   = (const float*)d_in[12];
    const float* bw   = (const float*)d_in[13];
    float* out = (float*)d_out;
    (void)in_sizes; (void)n_in; (void)out_size;

    __nv_bfloat16 *pq, *pk, *a1, *a2h, *a2l, *rr, *bqp, *bkp, *bwh, *bwl;
    float *pw;
    cudaGetSymbolAddress((void**)&pq,  g_q);
    cudaGetSymbolAddress((void**)&pk,  g_k);
    cudaGetSymbolAddress((void**)&pw,  g_w);
    cudaGetSymbolAddress((void**)&a1,  gA1);
    cudaGetSymbolAddress((void**)&a2h, gA2h);
    cudaGetSymbolAddress((void**)&a2l, gA2l);
    cudaGetSymbolAddress((void**)&rr,  gR);
    cudaGetSymbolAddress((void**)&bqp, gBq);
    cudaGetSymbolAddress((void**)&bkp, gBk);
    cudaGetSymbolAddress((void**)&bwh, gBwh);
    cudaGetSymbolAddress((void**)&bwl, gBwl);

    const int GEMM_SMEM = 65536;
    cudaFuncSetAttribute(hmma_gemm<false, __nv_bfloat16>, cudaFuncAttributeMaxDynamicSharedMemorySize, GEMM_SMEM);
    cudaFuncSetAttribute(hmma_gemm<true,  float>,         cudaFuncAttributeMaxDynamicSharedMemorySize, GEMM_SMEM);

    prep_idx_kernel<<<(NB + 255) / 256, 256>>>(draw);
    gather_kernel<<<NB, NEMB>>>(emb1, emb2);
    conv_r_kernel<<<(NB * NS * ND) / (256 * 4), 256>>>(r);
    transpose_kernel<false><<<dim3(SHD / 32, NEMB / 32), 256>>>(Wq, bqp, nullptr, NEMB, SHD);
    transpose_kernel<false><<<dim3(HD / 32, ND / 32),   256>>>(Wk, bkp, nullptr, ND,   HD);
    transpose_kernel<true ><<<dim3(HD / 32, NEMB / 32), 256>>>(Ww, bwh, bwl, NEMB, HD);

    // q = emb1[d] @ Wq + bq : single bf16 (feeds only softmax corrections)
    hmma_gemm<false, __nv_bfloat16><<<dim3(SHD / 128, NB / 128), 256, GEMM_SMEM>>>(
        a1, a1, bqp, bqp, bq, pq, SHD, NEMB, NEMB / 64);
    // k = r3 @ Wk + bk : single bf16
    hmma_gemm<false, __nv_bfloat16><<<dim3(HD / 128, (NB * NS) / 128), 256, GEMM_SMEM>>>(
        rr, rr, bkp, bkp, bk, pk, HD, ND, 1);
    // w = emb2[d] @ Ww + bw : 3-chunk split, fp32 out (multiplies output directly)
    hmma_gemm<true, float><<<dim3(HD / 128, NB / 128), 256, GEMM_SMEM>>>(
        a2h, a2l, bwh, bwl, bw, pw, HD, NEMB, NEMB / 64);

    attention1_kernel<<<dim3(NB, NH), 128>>>(r);
    attention2_kernel<<<dim3(NH, NB / 64), 256>>>(Wv, bv);
    reduce_kernel<<<1, 1024>>>();
    final_kernel<<<(NB * 32) / 256, 256>>>(emb2, Wb, bb, out);
}